// round 5
// baseline (speedup 1.0000x reference)
#include <cuda_runtime.h>
#include <math.h>

#define TT 1024
#define BB 512
#define KK 128
#define GG 2    // batches per block
#define NTH 256 // 128 j-columns x 2 i-halves

// ---- packed f32x2 helpers (sm_103a), NON-volatile so ptxas can schedule ----
__device__ __forceinline__ unsigned long long pk2(float a, float b) {
    unsigned long long r;
    asm("mov.b64 %0, {%1,%2};" : "=l"(r) : "f"(a), "f"(b));
    return r;
}
__device__ __forceinline__ void fma2(unsigned long long& d, unsigned long long a, unsigned long long b) {
    asm("fma.rn.f32x2 %0, %1, %2, %0;" : "+l"(d) : "l"(a), "l"(b));
}
__device__ __forceinline__ void upk2(unsigned long long v, float& a, float& b) {
    asm("mov.b64 {%0,%1}, %2;" : "=f"(a), "=f"(b) : "l"(v));
}

__device__ float g_negLogZ[BB];   // -logZ per batch (fwd writes, path reads)

// ---- forward recurrence: scaled linear domain, i-split packed-f32x2 matvec ----
// grid = BB/GG = 256 blocks, 256 threads, 2 CTAs/SM -> 4 warps/SMSP.
__global__ void __launch_bounds__(NTH, 2) crf_fwd_kernel(
    const float* __restrict__ em,      // [T,B,K]
    const float* __restrict__ mask,    // [T,B]
    const float* __restrict__ startT,  // [K]
    const float* __restrict__ trans,   // [K,K]
    const float* __restrict__ endT,    // [K]
    float* __restrict__ out)
{
    __shared__ alignas(16) float pv[2][GG][KK];  // [buf][batch][i] state
    __shared__ float2 ps[2][KK];                 // [half][j] partial sums (x=g0,y=g1)
    __shared__ float  wred[4][GG];

    const int tid  = threadIdx.x;
    const int j    = tid & (KK - 1);   // tag column owned
    const int h    = tid >> 7;         // i-half owned (0: i<64, 1: i>=64)
    const int warp = tid >> 5;
    const int lane = tid & 31;
    const int b0   = blockIdx.x * GG;

    if (blockIdx.x == 0 && tid == 0) out[0] = 0.0f;  // zero for launch-2 atomics

    // E half-column packed over i: epk[m] = (exp(E[h*64+2m][j]), exp(E[h*64+2m+1][j]))
    unsigned long long epk[32];
#pragma unroll
    for (int m = 0; m < 32; m++) {
        const int i = h * 64 + 2 * m;
        epk[m] = pk2(__expf(trans[i * KK + j]),
                     __expf(trans[(i + 1) * KK + j]));
    }

    float u[GG];
    int   Ce[GG];
    const float sj = startT[j];
#pragma unroll
    for (int g = 0; g < GG; g++) {
        u[g]  = __expf(sj + em[(b0 + g) * KK + j]);   // both halves compute identically
        Ce[g] = 0;
        if (h == 0) pv[1][g][j] = u[g];               // step t=1 reads buffer 1
    }
    __syncthreads();

    for (int t = 1; t < TT; t++) {
        const int r = t & 1, w = r ^ 1;

        // this step's global loads (consumed after the matvec)
        float eraw[GG], mv[GG];
#pragma unroll
        for (int g = 0; g < GG; g++) {
            eraw[g] = __ldg(&em[(t * BB + b0 + g) * KK + j]);
            mv[g]   = __ldg(&mask[t * BB + b0 + g]);
        }

        // half-matvec: P[g] = sum_{i in half h} u_prev[g][i] * E[i][j]
        unsigned long long acc0[GG], acc1[GG];
#pragma unroll
        for (int g = 0; g < GG; g++) { acc0[g] = 0ull; acc1[g] = 0ull; }
        const int ibase = h * 64;
#pragma unroll
        for (int k = 0; k < 16; k++) {
#pragma unroll
            for (int g = 0; g < GG; g++) {
                const ulonglong2 q = *(const ulonglong2*)&pv[r][g][ibase + 4 * k];  // LDS.128 bcast
                fma2(acc0[g], epk[2 * k],     q.x);
                fma2(acc1[g], epk[2 * k + 1], q.y);
            }
        }

        float P[GG];
#pragma unroll
        for (int g = 0; g < GG; g++) {
            float a, b, c, d;
            upk2(acc0[g], a, b);
            upk2(acc1[g], c, d);
            P[g] = (a + b) + (c + d);
        }
        ps[h][j] = make_float2(P[0], P[1]);
        __syncthreads();

        // combine halves; both halves compute identical state update
        const float2 po = ps[h ^ 1][j];
        const float So[GG] = { po.x, po.y };
#pragma unroll
        for (int g = 0; g < GG; g++) {
            float S  = P[g] + So[g];
            float un = __expf(eraw[g]) * S;
            u[g] = (mv[g] != 0.0f) ? un : u[g];
        }

        // exact power-of-2 rescale every 8 steps
        if ((t & 7) == 0) {
#pragma unroll
            for (int g = 0; g < GG; g++) {
                float v = u[g];
                for (int o = 16; o; o >>= 1) v = fmaxf(v, __shfl_xor_sync(0xffffffffu, v, o));
                if (lane == 0 && warp < 4) wred[warp][g] = v;   // h=0 warps suffice (identical)
            }
            __syncthreads();
#pragma unroll
            for (int g = 0; g < GG; g++) {
                float m = fmaxf(fmaxf(wred[0][g], wred[1][g]),
                                fmaxf(wred[2][g], wred[3][g]));
                int e   = ilogbf(m);
                float s = __int_as_float((unsigned)(127 - e) << 23);  // exact 2^-e
                u[g]  *= s;
                Ce[g] += e;
            }
        }

        if (h == 0) {
#pragma unroll
            for (int g = 0; g < GG; g++) pv[w][g][j] = u[g];
        }
        __syncthreads();
    }

    // finalize: -logZ[b] (h=0 warps; u/Ce identical across halves)
    const float ezj = __expf(endT[j]);
#pragma unroll
    for (int g = 0; g < GG; g++) {
        float z = u[g] * ezj;
        for (int o = 16; o; o >>= 1) z += __shfl_xor_sync(0xffffffffu, z, o);
        if (lane == 0 && warp < 4) wred[warp][g] = z;
    }
    __syncthreads();
    if (tid < GG) {
        const int g = tid;
        float zsum  = wred[0][g] + wred[1][g] + wred[2][g] + wred[3][g];
        double logZ = (double)Ce[g] * 0.6931471805599453 + log((double)zsum);
        g_negLogZ[b0 + g] = (float)(-logZ);
    }
}

// ---- gold-path score + final combine: one block per batch ----
__global__ void __launch_bounds__(128) path_kernel(
    const float* __restrict__ em, const int* __restrict__ tags,
    const float* __restrict__ mask, const float* __restrict__ startT,
    const float* __restrict__ trans, const float* __restrict__ endT,
    float* __restrict__ out)
{
    __shared__ float sacc[4], smsum[4];
    const int b = blockIdx.x, tid = threadIdx.x, warp = tid >> 5, lane = tid & 31;
    float acc = 0.0f, msum = 0.0f;
    for (int t = tid; t < TT; t += 128) {
        int   tg = tags[t * BB + b];
        float m  = mask[t * BB + b];
        acc  += em[(t * BB + b) * KK + tg] * m;
        msum += m;
        if (t > 0) {
            int tp = tags[(t - 1) * BB + b];
            acc += trans[tp * KK + tg] * m;
        }
    }
    for (int o = 16; o; o >>= 1) {
        acc  += __shfl_xor_sync(0xffffffffu, acc, o);
        msum += __shfl_xor_sync(0xffffffffu, msum, o);
    }
    if (lane == 0) { sacc[warp] = acc; smsum[warp] = msum; }
    __syncthreads();
    if (tid == 0) {
        float a  = sacc[0] + sacc[1] + sacc[2] + sacc[3];
        float ms = smsum[0] + smsum[1] + smsum[2] + smsum[3];
        int cnt = (int)(ms + 0.5f); if (cnt < 1) cnt = 1;
        a += startT[tags[b]] + endT[tags[(cnt - 1) * BB + b]];
        atomicAdd(out, a + g_negLogZ[b]);
    }
}

extern "C" void kernel_launch(void* const* d_in, const int* in_sizes, int n_in,
                              void* d_out, int out_size) {
    const float* em     = (const float*)d_in[0];
    const int*   tags   = (const int*)  d_in[1];
    const float* mask   = (const float*)d_in[2];
    const float* startT = (const float*)d_in[3];
    const float* trans  = (const float*)d_in[4];
    const float* endT   = (const float*)d_in[5];
    float* out = (float*)d_out;

    crf_fwd_kernel<<<BB / GG, NTH>>>(em, mask, startT, trans, endT, out);
    path_kernel<<<BB, 128>>>(em, tags, mask, startT, trans, endT, out);
}

// round 6
// speedup vs baseline: 1.1512x; 1.1512x over previous
#include <cuda_runtime.h>
#include <math.h>

#define TT 1024
#define BB 512
#define KK 128
#define GG 2   // batches per block (occupancy 2 per SM)

// ---- packed f32x2 helpers (sm_103a), NON-volatile so ptxas can schedule ----
__device__ __forceinline__ unsigned long long pk2(float a, float b) {
    unsigned long long r;
    asm("mov.b64 %0, {%1,%2};" : "=l"(r) : "f"(a), "f"(b));
    return r;
}
__device__ __forceinline__ void fma2(unsigned long long& d, unsigned long long a, unsigned long long b) {
    asm("fma.rn.f32x2 %0, %1, %2, %0;" : "+l"(d) : "l"(a), "l"(b));
}
__device__ __forceinline__ void upk2(unsigned long long v, float& a, float& b) {
    asm("mov.b64 {%0,%1}, %2;" : "=f"(a), "=f"(b) : "l"(v));
}

__device__ float g_negLogZ[BB];   // -logZ per batch (fwd writes, path reads)

// ---- forward recurrence: scaled linear domain, packed-f32x2 matvec,
//      em/mask prefetched 2 steps ahead to hide DRAM latency ----
// grid = BB/GG = 256 blocks, 128 threads, 2 CTAs/SM.
__global__ void __launch_bounds__(128, 2) crf_fwd_kernel(
    const float* __restrict__ em,      // [T,B,K]
    const float* __restrict__ mask,    // [T,B]
    const float* __restrict__ startT,  // [K]
    const float* __restrict__ trans,   // [K,K]
    const float* __restrict__ endT,    // [K]
    float* __restrict__ out)
{
    __shared__ alignas(16) float pv[2][GG][KK];  // [buf][batch][i]
    __shared__ float wred[4][GG];

    const int j    = threadIdx.x;   // tag column owned by this thread
    const int warp = j >> 5;
    const int lane = j & 31;
    const int b0   = blockIdx.x * GG;

    if (blockIdx.x == 0 && j == 0) out[0] = 0.0f;  // zero for launch-2 atomics

    // E column pre-packed over i: epk[m] = (exp(trans[2m][j]), exp(trans[2m+1][j]))
    unsigned long long epk[KK / 2];
#pragma unroll
    for (int m = 0; m < KK / 2; m++) {
        epk[m] = pk2(__expf(trans[(2 * m) * KK + j]),
                     __expf(trans[(2 * m + 1) * KK + j]));
    }

    float u[GG];
    int   Ce[GG];
    const float sj = startT[j];
#pragma unroll
    for (int g = 0; g < GG; g++) {
        u[g]  = __expf(sj + em[(b0 + g) * KK + j]);
        Ce[g] = 0;
        pv[1][g][j] = u[g];     // step t=1 reads buffer (t&1)=1
    }
    __syncthreads();

    // ---- 2-deep register prefetch pipeline for em/mask ----
    float ecur[GG], enext[GG], mcur[GG], mnext[GG];
#pragma unroll
    for (int g = 0; g < GG; g++) {
        ecur[g]  = __ldg(&em[(1 * BB + b0 + g) * KK + j]);
        mcur[g]  = __ldg(&mask[1 * BB + b0 + g]);
        enext[g] = __ldg(&em[(2 * BB + b0 + g) * KK + j]);
        mnext[g] = __ldg(&mask[2 * BB + b0 + g]);
    }

    for (int t = 1; t < TT; t++) {
        const int r = t & 1, w = r ^ 1;

        // kick off loads for t+2 (clamped; tail values discarded)
        const int tp = (t + 2 < TT) ? (t + 2) : (TT - 1);
        float epre[GG], mpre[GG];
#pragma unroll
        for (int g = 0; g < GG; g++) {
            epre[g] = __ldg(&em[(tp * BB + b0 + g) * KK + j]);
            mpre[g] = __ldg(&mask[tp * BB + b0 + g]);
        }

        // matvec: S[g] = sum_i u_prev[g][i] * E[i][j]; 4 independent acc chains
        unsigned long long acc0[GG], acc1[GG];
#pragma unroll
        for (int g = 0; g < GG; g++) { acc0[g] = 0ull; acc1[g] = 0ull; }
#pragma unroll
        for (int k = 0; k < KK / 4; k++) {
#pragma unroll
            for (int g = 0; g < GG; g++) {
                const ulonglong2 q = *(const ulonglong2*)&pv[r][g][4 * k];  // LDS.128 broadcast
                fma2(acc0[g], epk[2 * k],     q.x);
                fma2(acc1[g], epk[2 * k + 1], q.y);
            }
        }

#pragma unroll
        for (int g = 0; g < GG; g++) {
            float a, b, c, d;
            upk2(acc0[g], a, b);
            upk2(acc1[g], c, d);
            float S  = (a + b) + (c + d);
            float un = __expf(ecur[g]) * S;
            u[g] = (mcur[g] != 0.0f) ? un : u[g];
        }

        // rotate the prefetch pipeline
#pragma unroll
        for (int g = 0; g < GG; g++) {
            ecur[g]  = enext[g];  mcur[g]  = mnext[g];
            enext[g] = epre[g];   mnext[g] = mpre[g];
        }

        // exact power-of-2 rescale every 8 steps
        if ((t & 7) == 0) {
            float wm[GG];
#pragma unroll
            for (int g = 0; g < GG; g++) {
                float v = u[g];
                for (int o = 16; o; o >>= 1) v = fmaxf(v, __shfl_xor_sync(0xffffffffu, v, o));
                wm[g] = v;
            }
            if (lane == 0) {
#pragma unroll
                for (int g = 0; g < GG; g++) wred[warp][g] = wm[g];
            }
            __syncthreads();
#pragma unroll
            for (int g = 0; g < GG; g++) {
                float m = fmaxf(fmaxf(wred[0][g], wred[1][g]),
                                fmaxf(wred[2][g], wred[3][g]));
                int e   = ilogbf(m);
                float s = __int_as_float((unsigned)(127 - e) << 23);  // exact 2^-e
                u[g]  *= s;
                Ce[g] += e;
            }
        }

#pragma unroll
        for (int g = 0; g < GG; g++) pv[w][g][j] = u[g];
        __syncthreads();
    }

    // finalize: -logZ[b] = -(Ce*ln2 + log(sum_j u[j]*exp(end[j])))
    const float ezj = __expf(endT[j]);
#pragma unroll
    for (int g = 0; g < GG; g++) {
        float z = u[g] * ezj;
        for (int o = 16; o; o >>= 1) z += __shfl_xor_sync(0xffffffffu, z, o);
        if (lane == 0) wred[warp][g] = z;
    }
    __syncthreads();
    if (j < GG) {
        const int g = j;
        float zsum  = wred[0][g] + wred[1][g] + wred[2][g] + wred[3][g];
        double logZ = (double)Ce[g] * 0.6931471805599453 + log((double)zsum);
        g_negLogZ[b0 + g] = (float)(-logZ);
    }
}

// ---- gold-path score + final combine: one block per batch ----
__global__ void __launch_bounds__(128) path_kernel(
    const float* __restrict__ em, const int* __restrict__ tags,
    const float* __restrict__ mask, const float* __restrict__ startT,
    const float* __restrict__ trans, const float* __restrict__ endT,
    float* __restrict__ out)
{
    __shared__ float sacc[4], smsum[4];
    const int b = blockIdx.x, tid = threadIdx.x, warp = tid >> 5, lane = tid & 31;
    float acc = 0.0f, msum = 0.0f;
    for (int t = tid; t < TT; t += 128) {
        int   tg = tags[t * BB + b];
        float m  = mask[t * BB + b];
        acc  += em[(t * BB + b) * KK + tg] * m;
        msum += m;
        if (t > 0) {
            int tp = tags[(t - 1) * BB + b];
            acc += trans[tp * KK + tg] * m;
        }
    }
    for (int o = 16; o; o >>= 1) {
        acc  += __shfl_xor_sync(0xffffffffu, acc, o);
        msum += __shfl_xor_sync(0xffffffffu, msum, o);
    }
    if (lane == 0) { sacc[warp] = acc; smsum[warp] = msum; }
    __syncthreads();
    if (tid == 0) {
        float a  = sacc[0] + sacc[1] + sacc[2] + sacc[3];
        float ms = smsum[0] + smsum[1] + smsum[2] + smsum[3];
        int cnt = (int)(ms + 0.5f); if (cnt < 1) cnt = 1;
        a += startT[tags[b]] + endT[tags[(cnt - 1) * BB + b]];
        atomicAdd(out, a + g_negLogZ[b]);
    }
}

extern "C" void kernel_launch(void* const* d_in, const int* in_sizes, int n_in,
                              void* d_out, int out_size) {
    const float* em     = (const float*)d_in[0];
    const int*   tags   = (const int*)  d_in[1];
    const float* mask   = (const float*)d_in[2];
    const float* startT = (const float*)d_in[3];
    const float* trans  = (const float*)d_in[4];
    const float* endT   = (const float*)d_in[5];
    float* out = (float*)d_out;

    crf_fwd_kernel<<<BB / GG, KK>>>(em, mask, startT, trans, endT, out);
    path_kernel<<<BB, 128>>>(em, tags, mask, startT, trans, endT, out);
}